// round 3
// baseline (speedup 1.0000x reference)
#include <cuda_runtime.h>
#include <cuda_bf16.h>

// Retrace loss, single fused kernel with smem-staged coalesced loads.
//  per row b (B=4096), stride S=1025, T=1024:
//    c[k]   = clip(tp[b,k]/bp[b,k], 1e-10, 1.0)
//    A[j] = r[b,j+1] + 0.99*eQ[b,j+2] - (0.99*c[j+2])*tQ[b,j+2]   (j=0..1022)
//    B[j] = 0.99*c[j+2]
//    y[1023] = Q[b,1024];  y[j] = A[j] + B[j]*y[j+1]
//    loss += sum_j (Q[b,j]-y[j])^2
//  out = loss / (4096*1024)
//
// Backward recurrence = suffix scan of affine maps:
//   (A1,B1) o (A2,B2) = (A1 + B1*A2, B1*B2)
// Global loads: stride-256 cyclic per thread (fully coalesced), stored into
// smem pre-shifted so the scan phase reads float4-aligned, conflict-free.

#define S_STRIDE 1025
#define T_LEN    1024
#define NROWS    4096
#define GAMMA_F  0.99f
#define EPS_F    1e-10f
#define NTHREADS 256
#define ITEMS    4   // 256*4 = 1024 slots; slot 1023 = identity pad

__device__ double   g_part[NROWS];
__device__ unsigned g_count = 0;   // wraps 0..4095 via atomicInc -> deterministic across replays

struct Aff { float a, b; };

__device__ __forceinline__ Aff comp(Aff f, Aff g) {
    // f o g : apply g first, then f
    Aff r;
    r.a = fmaf(f.b, g.a, f.a);
    r.b = f.b * g.b;
    return r;
}

__global__ void __launch_bounds__(NTHREADS)
retrace_kernel(const float* __restrict__ Q,
               const float* __restrict__ eQ,
               const float* __restrict__ tQ,
               const float* __restrict__ r,
               const float* __restrict__ tp,
               const float* __restrict__ bp,
               float* __restrict__ out)
{
    __shared__ __align__(16) float sQ[T_LEN + 1];  // Q cols 0..1024
    __shared__ __align__(16) float sR[T_LEN];      // sR[j] = r [col j+1], j=0..1022
    __shared__ __align__(16) float sE[T_LEN];      // sE[j] = eQ[col j+2]
    __shared__ __align__(16) float sT[T_LEN];      // sT[j] = tQ[col j+2]
    __shared__ __align__(16) float sP[T_LEN];      // sP[j] = tp[col j+2]
    __shared__ __align__(16) float sPB[T_LEN];     // sPB[j]= bp[col j+2]

    const int row = blockIdx.x;
    const long base = (long)row * S_STRIDE;
    const int t = threadIdx.x;
    const unsigned lane = t & 31u;
    const unsigned w = t >> 5;

    // ---- coalesced staging: thread t covers indices t, t+256, t+512, t+768
#pragma unroll
    for (int p = 0; p < 4; p++) {
        const int i = t + p * NTHREADS;       // 0..1023
        sQ[i] = __ldg(&Q[base + i]);
        if (i < T_LEN - 1) {                  // only i==1023 excluded
            sR[i]  = __ldg(&r [base + i + 1]);
            sE[i]  = __ldg(&eQ[base + i + 2]);
            sT[i]  = __ldg(&tQ[base + i + 2]);
            sP[i]  = __ldg(&tp[base + i + 2]);
            sPB[i] = __ldg(&bp[base + i + 2]);
        }
    }
    if (t == 0) sQ[T_LEN] = __ldg(&Q[base + T_LEN]);
    __syncthreads();

    // ---- float4-aligned, conflict-free smem reads (thread t -> cols 4t..4t+3)
    const float4 q4  = reinterpret_cast<const float4*>(sQ )[t];
    const float4 r4  = reinterpret_cast<const float4*>(sR )[t];
    const float4 e4  = reinterpret_cast<const float4*>(sE )[t];
    const float4 tq4 = reinterpret_cast<const float4*>(sT )[t];
    const float4 p4  = reinterpret_cast<const float4*>(sP )[t];
    const float4 b4  = reinterpret_cast<const float4*>(sPB)[t];
    const float init = sQ[T_LEN];

    float qv[ITEMS]  = {q4.x,  q4.y,  q4.z,  q4.w};
    float rv[ITEMS]  = {r4.x,  r4.y,  r4.z,  r4.w};
    float ev[ITEMS]  = {e4.x,  e4.y,  e4.z,  e4.w};
    float tqv[ITEMS] = {tq4.x, tq4.y, tq4.z, tq4.w};
    float ptv[ITEMS] = {p4.x,  p4.y,  p4.z,  p4.w};
    float pbv[ITEMS] = {b4.x,  b4.y,  b4.z,  b4.w};

    const int j0 = t * ITEMS;

    // ---- build local affine maps (slot 1023 = identity; its smem was garbage, discarded)
    Aff loc[ITEMS];
#pragma unroll
    for (int k = 0; k < ITEMS; k++) {
        if (j0 + k < T_LEN - 1) {
            const float c = fminf(fmaxf(__fdividef(ptv[k], pbv[k]), EPS_F), 1.0f);
            const float B = GAMMA_F * c;
            loc[k].b = B;
            loc[k].a = fmaf(GAMMA_F, ev[k], rv[k]) - B * tqv[k];
        } else {
            loc[k].a = 0.0f; loc[k].b = 1.0f;
        }
    }

    // ---- per-thread local suffix composition
    Aff suf[ITEMS];
    suf[ITEMS - 1] = loc[ITEMS - 1];
#pragma unroll
    for (int k = ITEMS - 2; k >= 0; k--) suf[k] = comp(loc[k], suf[k + 1]);

    // ---- warp-level inclusive suffix scan of thread aggregates
    Aff v = suf[0];
#pragma unroll
    for (int off = 1; off < 32; off <<= 1) {
        float oa = __shfl_down_sync(0xffffffffu, v.a, off);
        float ob = __shfl_down_sync(0xffffffffu, v.b, off);
        if (lane + off < 32) { Aff g; g.a = oa; g.b = ob; v = comp(v, g); }
    }

    // in-warp EXCLUSIVE suffix (threads lane+1..31)
    float ea = __shfl_down_sync(0xffffffffu, v.a, 1);
    float eb = __shfl_down_sync(0xffffffffu, v.b, 1);
    Aff inwexcl;
    if (lane == 31) { inwexcl.a = 0.0f; inwexcl.b = 1.0f; }
    else            { inwexcl.a = ea;   inwexcl.b = eb;   }

    __shared__ float swA[8], swB[8];   // warp inclusive totals
    __shared__ float exA[8], exB[8];   // per-warp exclusive suffixes
    if (lane == 0) { swA[w] = v.a; swB[w] = v.b; }
    __syncthreads();
    if (t == 0) {
        Aff acc; acc.a = 0.0f; acc.b = 1.0f;
        for (int ww = 7; ww >= 0; ww--) {
            exA[ww] = acc.a; exB[ww] = acc.b;
            Aff tot; tot.a = swA[ww]; tot.b = swB[ww];
            acc = comp(tot, acc);
        }
    }
    __syncthreads();

    Aff wex; wex.a = exA[w]; wex.b = exB[w];
    const Aff S = comp(inwexcl, wex);

    // ---- apply composed maps and accumulate squared error
    double lsum = 0.0;
#pragma unroll
    for (int k = 0; k < ITEMS; k++) {
        const Aff m = comp(suf[k], S);
        const float y = fmaf(m.b, init, m.a);
        const float d = qv[k] - y;
        lsum += (double)d * (double)d;
    }

    // ---- block reduction (double)
#pragma unroll
    for (int off = 16; off > 0; off >>= 1)
        lsum += __shfl_down_sync(0xffffffffu, lsum, off);
    __shared__ double ssum[8];
    if (lane == 0) ssum[w] = lsum;
    __syncthreads();

    __shared__ bool s_last;
    if (t == 0) {
        double x = 0.0;
#pragma unroll
        for (int i = 0; i < 8; i++) x += ssum[i];
        g_part[row] = x;
        __threadfence();
        unsigned old = atomicInc(&g_count, NROWS - 1);  // wraps to 0 after 4096 arrivals
        s_last = (old == NROWS - 1);
    }
    __syncthreads();

    // ---- last block reduces all partials and writes output
    if (s_last) {
        double x = 0.0;
        for (int i = t; i < NROWS; i += NTHREADS)
            x += __ldcg(&g_part[i]);
#pragma unroll
        for (int off = 16; off > 0; off >>= 1)
            x += __shfl_down_sync(0xffffffffu, x, off);
        __shared__ double fsum[8];
        if (lane == 0) fsum[w] = x;
        __syncthreads();
        if (t == 0) {
            double tot = 0.0;
#pragma unroll
            for (int i = 0; i < 8; i++) tot += fsum[i];
            out[0] = (float)(tot / (double)((long long)NROWS * T_LEN));
        }
    }
}

extern "C" void kernel_launch(void* const* d_in, const int* in_sizes, int n_in,
                              void* d_out, int out_size)
{
    const float* Q   = (const float*)d_in[0];
    const float* eQ  = (const float*)d_in[1];
    const float* tQ  = (const float*)d_in[2];
    const float* r   = (const float*)d_in[3];
    const float* tp  = (const float*)d_in[4];
    const float* bp  = (const float*)d_in[5];
    float* out = (float*)d_out;

    retrace_kernel<<<NROWS, NTHREADS>>>(Q, eQ, tQ, r, tp, bp, out);
}

// round 4
// speedup vs baseline: 1.2002x; 1.2002x over previous
#include <cuda_runtime.h>
#include <cuda_bf16.h>

// Retrace loss, single fused kernel. Warp-cyclic layout:
//   warp w owns cols [w*128, w*128+128); thread lane owns j = w*128 + p*32 + lane.
// -> every global load is consecutive-lane-consecutive-address (1 wavefront/warp),
//    and the scan stays register/shuffle-resident (no smem staging).
//
// Backward recurrence y[j] = A[j] + B[j]*y[j+1] solved as suffix composition of
// affine maps  (A1,B1) o (A2,B2) = (A1 + B1*A2, B1*B2):
//   4 independent 32-lane page scans (ILP) -> page-total compose -> cross-warp compose.

#define S_STRIDE 1025
#define T_LEN    1024
#define NROWS    4096
#define GAMMA_F  0.99f
#define EPS_F    1e-10f
#define NTHREADS 256
#define NPAGES   4

__device__ double   g_part[NROWS];
__device__ unsigned g_count = 0;   // wraps 0..4095 via atomicInc -> deterministic across replays

struct Aff { float a, b; };

__device__ __forceinline__ Aff comp(Aff f, Aff g) {
    // f o g : apply g first, then f
    Aff r;
    r.a = fmaf(f.b, g.a, f.a);
    r.b = f.b * g.b;
    return r;
}

__global__ void __launch_bounds__(NTHREADS)
retrace_kernel(const float* __restrict__ Q,
               const float* __restrict__ eQ,
               const float* __restrict__ tQ,
               const float* __restrict__ r,
               const float* __restrict__ tp,
               const float* __restrict__ bp,
               float* __restrict__ out)
{
    const int row = blockIdx.x;
    const long base = (long)row * S_STRIDE;
    const int t = threadIdx.x;
    const unsigned lane = t & 31u;
    const unsigned w = t >> 5;
    const int seg = (int)w * 128;

    int jj[NPAGES];
#pragma unroll
    for (int p = 0; p < NPAGES; p++) jj[p] = seg + p * 32 + (int)lane;
    // last element (w==7, p==3, lane==31) is j==1023 -> identity map

    // ---- phase 1 loads: tp/bp (coalesced; clamp +2 index for j==1023 to stay in-bounds)
    float ptv[NPAGES], pbv[NPAGES];
#pragma unroll
    for (int p = 0; p < NPAGES; p++) {
        const int i2 = (jj[p] < T_LEN - 1) ? jj[p] + 2 : T_LEN;  // unused value for j==1023
        ptv[p] = __ldg(&tp[base + i2]);
        pbv[p] = __ldg(&bp[base + i2]);
    }

    // ---- phase 2 loads: r/eQ/tQ
    float rv[NPAGES], ev[NPAGES], tqv[NPAGES];
#pragma unroll
    for (int p = 0; p < NPAGES; p++) {
        const int i2 = (jj[p] < T_LEN - 1) ? jj[p] + 2 : T_LEN;
        rv[p]  = __ldg(&r [base + jj[p] + 1]);   // j+1 <= 1024, always in-bounds
        ev[p]  = __ldg(&eQ[base + i2]);
        tqv[p] = __ldg(&tQ[base + i2]);
    }

    // ---- build per-element affine maps
    Aff f[NPAGES];
#pragma unroll
    for (int p = 0; p < NPAGES; p++) {
        if (jj[p] < T_LEN - 1) {
            const float c = fminf(fmaxf(__fdividef(ptv[p], pbv[p]), EPS_F), 1.0f);
            const float B = GAMMA_F * c;
            f[p].b = B;
            f[p].a = fmaf(GAMMA_F, ev[p], rv[p]) - B * tqv[p];
        } else {
            f[p].a = 0.0f; f[p].b = 1.0f;   // identity (j == 1023)
        }
    }

    // ---- 4 independent 32-lane inclusive suffix scans (interleaved for ILP)
    Aff s[NPAGES];
#pragma unroll
    for (int p = 0; p < NPAGES; p++) s[p] = f[p];
#pragma unroll
    for (int off = 1; off < 32; off <<= 1) {
#pragma unroll
        for (int p = 0; p < NPAGES; p++) {
            const float oa = __shfl_down_sync(0xffffffffu, s[p].a, off);
            const float ob = __shfl_down_sync(0xffffffffu, s[p].b, off);
            if (lane + off < 32) { Aff g; g.a = oa; g.b = ob; s[p] = comp(s[p], g); }
        }
    }
    // s[p] at lane l = f_{l} o ... o f_{31} within page p

    // ---- page totals (broadcast lane 0) and exclusive page suffixes
    Aff tpg[NPAGES];
#pragma unroll
    for (int p = 0; p < NPAGES; p++) {
        tpg[p].a = __shfl_sync(0xffffffffu, s[p].a, 0);
        tpg[p].b = __shfl_sync(0xffffffffu, s[p].b, 0);
    }
    Aff E[NPAGES];
    E[3].a = 0.0f; E[3].b = 1.0f;
    E[2] = tpg[3];
    E[1] = comp(tpg[2], E[2]);
    E[0] = comp(tpg[1], E[1]);
    const Aff warpTot = comp(tpg[0], E[0]);

    // ---- cross-warp exclusive suffix (8 warps)
    __shared__ float swA[8], swB[8];   // warp totals
    __shared__ float exA[8], exB[8];   // exclusive suffixes (warps after w)
    if (lane == 0) { swA[w] = warpTot.a; swB[w] = warpTot.b; }
    __syncthreads();
    if (t == 0) {
        Aff acc; acc.a = 0.0f; acc.b = 1.0f;
        for (int ww = 7; ww >= 0; ww--) {
            exA[ww] = acc.a; exB[ww] = acc.b;
            Aff tot; tot.a = swA[ww]; tot.b = swB[ww];
            acc = comp(tot, acc);
        }
    }
    __syncthreads();
    Aff W; W.a = exA[w]; W.b = exB[w];

    // ---- phase 3 loads: Q values + init
    float qv[NPAGES];
#pragma unroll
    for (int p = 0; p < NPAGES; p++) qv[p] = __ldg(&Q[base + jj[p]]);
    const float init = __ldg(&Q[base + T_LEN]);

    // ---- apply composed maps, accumulate squared error (fp32 locally)
    float fsum = 0.0f;
#pragma unroll
    for (int p = 0; p < NPAGES; p++) {
        const Aff R = comp(E[p], W);          // uniform per lane
        const Aff m = comp(s[p], R);          // f_j o ... o f_1023
        const float y = fmaf(m.b, init, m.a);
        const float d = qv[p] - y;
        fsum = fmaf(d, d, fsum);
    }

    // ---- warp reduction in fp32, cross-warp in double
#pragma unroll
    for (int off = 16; off > 0; off >>= 1)
        fsum += __shfl_down_sync(0xffffffffu, fsum, off);
    __shared__ double ssum[8];
    if (lane == 0) ssum[w] = (double)fsum;
    __syncthreads();

    __shared__ bool s_last;
    if (t == 0) {
        double x = 0.0;
#pragma unroll
        for (int i = 0; i < 8; i++) x += ssum[i];
        g_part[row] = x;
        __threadfence();
        unsigned old = atomicInc(&g_count, NROWS - 1);  // wraps to 0 after 4096 arrivals
        s_last = (old == NROWS - 1);
    }
    __syncthreads();

    // ---- last block reduces all partials and writes output
    if (s_last) {
        double x = 0.0;
        for (int i = t; i < NROWS; i += NTHREADS)
            x += __ldcg(&g_part[i]);
#pragma unroll
        for (int off = 16; off > 0; off >>= 1)
            x += __shfl_down_sync(0xffffffffu, x, off);
        __shared__ double fs2[8];
        if (lane == 0) fs2[w] = x;
        __syncthreads();
        if (t == 0) {
            double tot = 0.0;
#pragma unroll
            for (int i = 0; i < 8; i++) tot += fs2[i];
            out[0] = (float)(tot / (double)((long long)NROWS * T_LEN));
        }
    }
}

extern "C" void kernel_launch(void* const* d_in, const int* in_sizes, int n_in,
                              void* d_out, int out_size)
{
    const float* Q   = (const float*)d_in[0];
    const float* eQ  = (const float*)d_in[1];
    const float* tQ  = (const float*)d_in[2];
    const float* r   = (const float*)d_in[3];
    const float* tp  = (const float*)d_in[4];
    const float* bp  = (const float*)d_in[5];
    float* out = (float*)d_out;

    retrace_kernel<<<NROWS, NTHREADS>>>(Q, eQ, tQ, r, tp, bp, out);
}

// round 5
// speedup vs baseline: 1.2320x; 1.0264x over previous
#include <cuda_runtime.h>
#include <cuda_bf16.h>

// Retrace loss, single fused kernel.
// Layout: warp w owns cols [w*128, (w+1)*128).
//   Staging (coalesced): lane owns cols w*128 + p*32 + lane  -> build (A,B) maps
//     in registers, transpose A,B,Q through a warp-private smem slice (syncwarp only).
//   Scan (contiguous):   lane owns cols w*128 + 4*lane + k, k=0..3
//     serial suffix-compose 4, then ONE 32-lane warp suffix scan, then cross-warp.
// Affine composition: (A1,B1) o (A2,B2) = (A1 + B1*A2, B1*B2).

#define S_STRIDE 1025
#define T_LEN    1024
#define NROWS    4096
#define GAMMA_F  0.99f
#define EPS_F    1e-10f
#define NTHREADS 256

__device__ double   g_part[NROWS];
__device__ unsigned g_count = 0;   // wraps 0..4095 via atomicInc -> deterministic across replays

struct Aff { float a, b; };

__device__ __forceinline__ Aff comp(Aff f, Aff g) {
    // f o g : apply g first, then f
    Aff r;
    r.a = fmaf(f.b, g.a, f.a);
    r.b = f.b * g.b;
    return r;
}

__global__ void __launch_bounds__(NTHREADS)
retrace_kernel(const float* __restrict__ Q,
               const float* __restrict__ eQ,
               const float* __restrict__ tQ,
               const float* __restrict__ r,
               const float* __restrict__ tp,
               const float* __restrict__ bp,
               float* __restrict__ out)
{
    __shared__ __align__(16) float sA [8][128];
    __shared__ __align__(16) float sB [8][128];
    __shared__ __align__(16) float sQv[8][128];
    __shared__ float swA[8], swB[8], exA[8], exB[8];
    __shared__ double ssum[8];
    __shared__ bool s_last;

    const int row = blockIdx.x;
    const long base = (long)row * S_STRIDE;
    const int t = threadIdx.x;
    const unsigned lane = t & 31u;
    const unsigned w = t >> 5;
    const int seg = (int)w * 128;

    // ---- staging: coalesced loads, map construction in registers, warp-local transpose
#pragma unroll
    for (int p = 0; p < 4; p++) {
        const int il = p * 32 + (int)lane;          // 0..127 within warp segment
        const int i  = seg + il;                    // global col
        const int i2 = (i < T_LEN - 1) ? i + 2 : T_LEN;   // clamped (value unused if i==1023)
        const float rv  = __ldg(&r [base + i + 1]);       // i+1 <= 1024: in-bounds
        const float ev  = __ldg(&eQ[base + i2]);
        const float tqv = __ldg(&tQ[base + i2]);
        const float pt  = __ldg(&tp[base + i2]);
        const float pb  = __ldg(&bp[base + i2]);
        sQv[w][il] = __ldg(&Q[base + i]);
        float a, b;
        if (i < T_LEN - 1) {
            const float c = fminf(fmaxf(__fdividef(pt, pb), EPS_F), 1.0f);
            b = GAMMA_F * c;
            a = fmaf(GAMMA_F, ev, rv) - b * tqv;
        } else {                                    // i == 1023: identity map
            a = 0.0f; b = 1.0f;
        }
        sA[w][il] = a;
        sB[w][il] = b;
    }
    const float init = __ldg(&Q[base + T_LEN]);     // uniform -> broadcast load
    __syncwarp();

    // ---- contiguous read-back: lane owns cols seg + 4*lane .. +3
    const float4 a4 = reinterpret_cast<const float4*>(sA [w])[lane];
    const float4 b4 = reinterpret_cast<const float4*>(sB [w])[lane];
    const float4 q4 = reinterpret_cast<const float4*>(sQv[w])[lane];
    Aff loc[4] = { {a4.x, b4.x}, {a4.y, b4.y}, {a4.z, b4.z}, {a4.w, b4.w} };
    const float qv[4] = { q4.x, q4.y, q4.z, q4.w };

    // ---- serial suffix composition within thread (pure FMA)
    Aff suf[4];
    suf[3] = loc[3];
#pragma unroll
    for (int k = 2; k >= 0; k--) suf[k] = comp(loc[k], suf[k + 1]);

    // ---- single warp-level inclusive suffix scan of thread aggregates
    Aff v = suf[0];
#pragma unroll
    for (int off = 1; off < 32; off <<= 1) {
        const float oa = __shfl_down_sync(0xffffffffu, v.a, off);
        const float ob = __shfl_down_sync(0xffffffffu, v.b, off);
        if (lane + off < 32) { Aff g; g.a = oa; g.b = ob; v = comp(v, g); }
    }

    // in-warp EXCLUSIVE suffix (threads lane+1..31)
    const float ea = __shfl_down_sync(0xffffffffu, v.a, 1);
    const float eb = __shfl_down_sync(0xffffffffu, v.b, 1);
    Aff inwexcl;
    if (lane == 31) { inwexcl.a = 0.0f; inwexcl.b = 1.0f; }
    else            { inwexcl.a = ea;   inwexcl.b = eb;   }

    // ---- cross-warp exclusive suffix (8 warps)
    if (lane == 0) { swA[w] = v.a; swB[w] = v.b; }
    __syncthreads();
    if (t == 0) {
        Aff acc; acc.a = 0.0f; acc.b = 1.0f;
        for (int ww = 7; ww >= 0; ww--) {
            exA[ww] = acc.a; exB[ww] = acc.b;
            Aff tot; tot.a = swA[ww]; tot.b = swB[ww];
            acc = comp(tot, acc);
        }
    }
    __syncthreads();
    Aff W; W.a = exA[w]; W.b = exB[w];
    const Aff S = comp(inwexcl, W);      // everything after this thread's 4 elements

    // ---- apply composed maps, accumulate squared error (fp32 locally)
    float fsum = 0.0f;
#pragma unroll
    for (int k = 0; k < 4; k++) {
        const Aff m = comp(suf[k], S);   // f_j o ... o f_1023 (identities padded)
        const float y = fmaf(m.b, init, m.a);
        const float d = qv[k] - y;
        fsum = fmaf(d, d, fsum);
    }

    // ---- warp reduction in fp32, cross-warp in double
#pragma unroll
    for (int off = 16; off > 0; off >>= 1)
        fsum += __shfl_down_sync(0xffffffffu, fsum, off);
    if (lane == 0) ssum[w] = (double)fsum;
    __syncthreads();

    if (t == 0) {
        double x = 0.0;
#pragma unroll
        for (int i = 0; i < 8; i++) x += ssum[i];
        g_part[row] = x;
        __threadfence();
        const unsigned old = atomicInc(&g_count, NROWS - 1);  // wraps after 4096 arrivals
        s_last = (old == NROWS - 1);
    }
    __syncthreads();

    // ---- last block reduces all partials and writes output
    if (s_last) {
        double x = 0.0;
        for (int i = t; i < NROWS; i += NTHREADS)
            x += __ldcg(&g_part[i]);
#pragma unroll
        for (int off = 16; off > 0; off >>= 1)
            x += __shfl_down_sync(0xffffffffu, x, off);
        __shared__ double fs2[8];
        if (lane == 0) fs2[w] = x;
        __syncthreads();
        if (t == 0) {
            double tot = 0.0;
#pragma unroll
            for (int i = 0; i < 8; i++) tot += fs2[i];
            out[0] = (float)(tot / (double)((long long)NROWS * T_LEN));
        }
    }
}

extern "C" void kernel_launch(void* const* d_in, const int* in_sizes, int n_in,
                              void* d_out, int out_size)
{
    const float* Q   = (const float*)d_in[0];
    const float* eQ  = (const float*)d_in[1];
    const float* tQ  = (const float*)d_in[2];
    const float* r   = (const float*)d_in[3];
    const float* tp  = (const float*)d_in[4];
    const float* bp  = (const float*)d_in[5];
    float* out = (float*)d_out;

    retrace_kernel<<<NROWS, NTHREADS>>>(Q, eQ, tQ, r, tp, bp, out);
}